// round 13
// baseline (speedup 1.0000x reference)
#include <cuda_runtime.h>
#include <math.h>

#define N       12288
#define D_K     8
#define H1      32
#define H2      16
#define N_EDGES 6144
#define N_TRI   4096
#define CAP     64
#define ECAP    32
#define NB      192
#define TPB     256
#define RPB     64    // rows per block (TPB/4)

// ---------------- device scratch (zero-initialized at module load) ----------------
__device__ float    g_kv[N_TRI * CAP * 16];  // per-slot: k[0:8), v[8:16)
__device__ float    g_logits[N];
__device__ int      g_cnt[N_TRI];           // returns to 0 every call (tri completion)
__device__ int      g_tdone[N_TRI];         // returns to 0 every call
__device__ int      g_ecnt[N_EDGES];        // returns to 0 every call (edge completion)
__device__ int      g_edone[N_EDGES];       // returns to 0 every call
__device__ int      g_emem[N_EDGES * ECAP];
__device__ unsigned g_bar1;                 // monotonic ticket counter (never reset)

__device__ __forceinline__ float gelu_exact(float x) {
    return 0.5f * x * (1.0f + erff(x * 0.70710678118654752f));
}

// acq_rel gpu-scope atomic add: release orders prior stores (logit) before the
// RMW; acquire orders subsequent loads after it. No CCTL.IVALL L1 flush.
__device__ __forceinline__ int atom_add_acqrel(int* p, int v) {
    int old;
    asm volatile("atom.acq_rel.gpu.global.add.s32 %0, [%1], %2;"
                 : "=r"(old) : "l"(p), "r"(v) : "memory");
    return old;
}

// ticket grid barrier — monotonic across graph replays, no reset required.
// safe: launch_bounds(256,2) -> 2 blocks/SM schedulable, 192 <= 148*2,
// so the whole grid is strictly one co-resident wave.
__device__ __forceinline__ void grid_barrier_ticket(unsigned* ctr) {
    __syncthreads();
    if (threadIdx.x == 0) {
        __threadfence();
        unsigned t0 = atomicAdd(ctr, 1u);
        unsigned target = t0 - (t0 % NB) + NB;
        while (*(volatile unsigned*)ctr < target) {}
        __threadfence();
    }
    __syncthreads();
}

__global__ __launch_bounds__(TPB, 2)
void k_fused(const float* __restrict__ ef, const int* __restrict__ eids,
             const int* __restrict__ tri,
             const float* __restrict__ Wq, const float* __restrict__ bq,
             const float* __restrict__ Wk, const float* __restrict__ bk,
             const float* __restrict__ Wv, const float* __restrict__ bv,
             const float* __restrict__ W1, const float* __restrict__ b1,
             const float* __restrict__ ln1g, const float* __restrict__ ln1b,
             const float* __restrict__ rmsw,
             const float* __restrict__ Wr, const float* __restrict__ br,
             const float* __restrict__ ln2g, const float* __restrict__ ln2b,
             const float* __restrict__ W2, const float* __restrict__ b2,
             const float* __restrict__ W3, const float* __restrict__ b3,
             float* __restrict__ out) {
    // padded shared weights (odd strides -> conflict-free for 4-lane groups)
    __shared__ float sW1[H1 * 9];        // [o*9 + k], k<8
    __shared__ float sWr[H1 * 33];       // [o*33 + k], k<32
    __shared__ float sW2[H2 * 33];       // [o*33 + k], k<32
    __shared__ float sb1[H1], sg1[H1], sB1[H1], srw[H1], sbr[H1], sg2[H1], sB2[H1];
    __shared__ float sb2[H2], sW3[H2];
    __shared__ float sb3;
    __shared__ float sh[RPB * 33];       // per-row 32-vector scratch, padded

    const int tid = threadIdx.x;
    const int sub = tid & 3;             // lane within 4-lane row group
    const int rl  = tid >> 2;            // local row
    const int i   = blockIdx.x * RPB + rl;
    const int lane = tid & 31;
    const unsigned gmask = 0xFu << (lane & ~3);   // this group's shuffle mask

    // ---- stage weights (overlaps phase 1; consumed only after the barrier) ----
    for (int j = tid; j < H1 * D_K; j += TPB) sW1[(j >> 3) * 9  + (j & 7)]  = W1[j];
    for (int j = tid; j < H1 * H1;  j += TPB) sWr[(j >> 5) * 33 + (j & 31)] = Wr[j];
    for (int j = tid; j < H2 * H1;  j += TPB) sW2[(j >> 5) * 33 + (j & 31)] = W2[j];
    if (tid < H1) {
        sb1[tid] = b1[tid];   sg1[tid] = ln1g[tid]; sB1[tid] = ln1b[tid];
        srw[tid] = rmsw[tid]; sbr[tid] = br[tid];
        sg2[tid] = ln2g[tid]; sB2[tid] = ln2b[tid];
    }
    if (tid < H2) { sb2[tid] = b2[tid]; sW3[tid] = W3[tid]; }
    if (tid == 0) sb3 = b3[0];

    // ============ Phase 1: qkv (2 dims/lane) + slot-indexed k/v store ========
    float2 qv;                            // kept live for phase 2
    const int t = tri[i];
    const int e = eids[i];
    {
        float x0 = ef[2 * i + 0];
        float x1 = ef[2 * i + 1];
        int o0 = 2 * sub;
        float2 kv, vv;
        qv.x = fmaf(x0, Wq[o0*2],     fmaf(x1, Wq[o0*2+1],     bq[o0]));
        qv.y = fmaf(x0, Wq[(o0+1)*2], fmaf(x1, Wq[(o0+1)*2+1], bq[o0+1]));
        kv.x = fmaf(x0, Wk[o0*2],     fmaf(x1, Wk[o0*2+1],     bk[o0]));
        kv.y = fmaf(x0, Wk[(o0+1)*2], fmaf(x1, Wk[(o0+1)*2+1], bk[o0+1]));
        vv.x = fmaf(x0, Wv[o0*2],     fmaf(x1, Wv[o0*2+1],     bv[o0]));
        vv.y = fmaf(x0, Wv[(o0+1)*2], fmaf(x1, Wv[(o0+1)*2+1], bv[o0+1]));
        int p = 0;
        if (sub == 0) {
            p = atomicAdd(&g_cnt[t], 1);
            int pe = atomicAdd(&g_ecnt[e], 1);
            if (pe < ECAP) g_emem[e * ECAP + pe] = i;
        }
        p = __shfl_sync(gmask, p, 0, 4);
        if (p < CAP) {
            float2* dst = (float2*)&g_kv[((size_t)t * CAP + p) * 16];
            dst[sub]     = kv;            // k dims [2sub, 2sub+1]
            dst[4 + sub] = vv;            // v dims [2sub, 2sub+1]
        }
    }

    grid_barrier_ticket(&g_bar1);

    // ====== Phase 2: attention + MLP -> logits + dataflow completions ======
    {
        // full q[8] to every lane via intra-group broadcast
        float q[D_K];
#pragma unroll
        for (int s2 = 0; s2 < 4; s2++) {
            q[2*s2]   = __shfl_sync(gmask, qv.x, s2, 4);
            q[2*s2+1] = __shfl_sync(gmask, qv.y, s2, 4);
        }

        const float isq = 0.35355339059327373f;  // 1/sqrt(8)
        const float4* kvb = (const float4*)&g_kv[(size_t)t * CAP * 16];

        // issue count loads AND first-slot kv loads in parallel (no dependency):
        // slots beyond c hold stale data but their contribution is predicated to 0.
        const int cc  = g_cnt[t];            // final after barrier
        const int tot = g_ecnt[e];           // final after barrier
        float4 ka = kvb[sub * 4 + 0];
        float4 kb = kvb[sub * 4 + 1];
        float4 va = kvb[sub * 4 + 2];
        float4 vb = kvb[sub * 4 + 3];
        const int c = min(cc, CAP);

        float se = 0.0f, acc[D_K];
#pragma unroll
        for (int o = 0; o < D_K; o++) acc[o] = 0.0f;
        {
            float p = q[0]*ka.x + q[1]*ka.y + q[2]*ka.z + q[3]*ka.w
                    + q[4]*kb.x + q[5]*kb.y + q[6]*kb.z + q[7]*kb.w;
            float ex = (sub < c) ? __expf(p * isq) : 0.0f;
            se += ex;
            acc[0] = fmaf(ex, va.x, acc[0]); acc[1] = fmaf(ex, va.y, acc[1]);
            acc[2] = fmaf(ex, va.z, acc[2]); acc[3] = fmaf(ex, va.w, acc[3]);
            acc[4] = fmaf(ex, vb.x, acc[4]); acc[5] = fmaf(ex, vb.y, acc[5]);
            acc[6] = fmaf(ex, vb.z, acc[6]); acc[7] = fmaf(ex, vb.w, acc[7]);
        }
        for (int jj = sub + 4; jj < c; jj += 4) {   // rare tail (c > 4)
            float4 ka2 = kvb[jj * 4 + 0];
            float4 kb2 = kvb[jj * 4 + 1];
            float4 va2 = kvb[jj * 4 + 2];
            float4 vb2 = kvb[jj * 4 + 3];
            float p = q[0]*ka2.x + q[1]*ka2.y + q[2]*ka2.z + q[3]*ka2.w
                    + q[4]*kb2.x + q[5]*kb2.y + q[6]*kb2.z + q[7]*kb2.w;
            float ex = __expf(p * isq);
            se += ex;
            acc[0] = fmaf(ex, va2.x, acc[0]); acc[1] = fmaf(ex, va2.y, acc[1]);
            acc[2] = fmaf(ex, va2.z, acc[2]); acc[3] = fmaf(ex, va2.w, acc[3]);
            acc[4] = fmaf(ex, vb2.x, acc[4]); acc[5] = fmaf(ex, vb2.y, acc[5]);
            acc[6] = fmaf(ex, vb2.z, acc[6]); acc[7] = fmaf(ex, vb2.w, acc[7]);
        }
        // triangle completion ticket (reads of g_kv for t are done; relaxed ok)
        int dt = 0;
        if (sub == 0) dt = atomicAdd(&g_tdone[t], 1);

        se += __shfl_xor_sync(gmask, se, 1);
        se += __shfl_xor_sync(gmask, se, 2);
#pragma unroll
        for (int o = 0; o < D_K; o++) {
            acc[o] += __shfl_xor_sync(gmask, acc[o], 1);
            acc[o] += __shfl_xor_sync(gmask, acc[o], 2);
        }
        float inv_se = 1.0f / se;
        float att[D_K];
#pragma unroll
        for (int o = 0; o < D_K; o++) att[o] = acc[o] * inv_se;

        // ---- MLP: this lane owns outputs o = 8*sub .. 8*sub+7 ----
        const int ob = 8 * sub;
        float h[8];
#pragma unroll
        for (int oi = 0; oi < 8; oi++) {
            int o = ob + oi;
            float s = sb1[o];
#pragma unroll
            for (int kk = 0; kk < D_K; kk++) s = fmaf(att[kk], sW1[o * 9 + kk], s);
            h[oi] = s;
        }
        // layernorm 1 + gelu (one-round: concurrent sum & sumsq trees)
        {
            float ls = 0.0f, lq = 0.0f;
#pragma unroll
            for (int oi = 0; oi < 8; oi++) { ls += h[oi]; lq = fmaf(h[oi], h[oi], lq); }
            ls += __shfl_xor_sync(gmask, ls, 1);
            lq += __shfl_xor_sync(gmask, lq, 1);
            ls += __shfl_xor_sync(gmask, ls, 2);
            lq += __shfl_xor_sync(gmask, lq, 2);
            float mu  = ls * (1.0f / H1);
            float var = fmaf(-mu, mu, lq * (1.0f / H1));   // E[x^2] - mu^2
            float inv = rsqrtf(var + 1e-5f);
#pragma unroll
            for (int oi = 0; oi < 8; oi++)
                h[oi] = gelu_exact((h[oi] - mu) * inv * sg1[ob + oi] + sB1[ob + oi]);
        }
        // rmsnorm -> shared -> linear -> relu -> residual
        {
            float ss = 0.0f;
#pragma unroll
            for (int oi = 0; oi < 8; oi++) ss = fmaf(h[oi], h[oi], ss);
            ss += __shfl_xor_sync(gmask, ss, 1);
            ss += __shfl_xor_sync(gmask, ss, 2);
            float rms = sqrtf(ss * (1.0f / H1));
            float rinv = 1.0f / (rms + 1e-6f);
#pragma unroll
            for (int oi = 0; oi < 8; oi++)
                sh[rl * 33 + ob + oi] = h[oi] * rinv * srw[ob + oi];
            __syncwarp();
#pragma unroll
            for (int oi = 0; oi < 8; oi++) {
                int o = ob + oi;
                float s = sbr[o];
#pragma unroll
                for (int kk = 0; kk < H1; kk++)
                    s = fmaf(sh[rl * 33 + kk], sWr[o * 33 + kk], s);
                h[oi] += fmaxf(s, 0.0f);
            }
        }
        // layernorm 2 (one-round)
        {
            float ls = 0.0f, lq = 0.0f;
#pragma unroll
            for (int oi = 0; oi < 8; oi++) { ls += h[oi]; lq = fmaf(h[oi], h[oi], lq); }
            ls += __shfl_xor_sync(gmask, ls, 1);
            lq += __shfl_xor_sync(gmask, lq, 1);
            ls += __shfl_xor_sync(gmask, ls, 2);
            lq += __shfl_xor_sync(gmask, lq, 2);
            float mu  = ls * (1.0f / H1);
            float var = fmaf(-mu, mu, lq * (1.0f / H1));
            float inv = rsqrtf(var + 1e-5f);
#pragma unroll
            for (int oi = 0; oi < 8; oi++)
                h[oi] = (h[oi] - mu) * inv * sg2[ob + oi] + sB2[ob + oi];
        }
        // publish h, then linear 32->16 + gelu + linear 16->1 (4 outputs/lane)
        __syncwarp();
#pragma unroll
        for (int oi = 0; oi < 8; oi++) sh[rl * 33 + ob + oi] = h[oi];
        __syncwarp();
        float part = 0.0f;
#pragma unroll
        for (int oi = 0; oi < 4; oi++) {
            int o = 4 * sub + oi;
            float s = sb2[o];
#pragma unroll
            for (int kk = 0; kk < H1; kk++)
                s = fmaf(sh[rl * 33 + kk], sW2[o * 33 + kk], s);
            part = fmaf(gelu_exact(s), sW3[o], part);
        }
        part += __shfl_xor_sync(gmask, part, 1);
        part += __shfl_xor_sync(gmask, part, 2);
        // all 4 lanes now hold the full logit
        float lg = part + sb3;

        // ---- publish logit + edge completion (acq_rel atomic, no L1 flush) ----
        int elast = 0;
        if (sub == 0) {
            g_logits[i] = lg;                      // write-through to L2
            int d = atom_add_acqrel(&g_edone[e], 1);  // release: logit ordered first
            elast = (d == tot - 1);
            // triangle completion: all members have read g_cnt/g_kv by now
            if (dt == cc - 1) { g_cnt[t] = 0; g_tdone[t] = 0; }
        }
        elast = __shfl_sync(gmask, elast, 0, 4);

        if (elast) {
            // acquire half of the RMW ordered our subsequent loads; each
            // g_logits[j] is read exactly once per SM per launch -> no stale L1
            int m = min(tot, ECAP);
            float lv[8];
            int   jx[8];
            int   n = 0;
            float mx = -1e30f;
            for (int jj = sub; jj < m; jj += 4) {
                int j = g_emem[e * ECAP + jj];
                float l = g_logits[j];
                jx[n] = j; lv[n] = l; n++;
                mx = fmaxf(mx, l);
            }
            mx = fmaxf(mx, __shfl_xor_sync(gmask, mx, 1));
            mx = fmaxf(mx, __shfl_xor_sync(gmask, mx, 2));
            float s = 0.0f;
            for (int u = 0; u < n; u++) { lv[u] = __expf(lv[u] - mx); s += lv[u]; }
            s += __shfl_xor_sync(gmask, s, 1);
            s += __shfl_xor_sync(gmask, s, 2);
            float inv = 1.0f / s;
            for (int u = 0; u < n; u++) out[jx[u]] = lv[u] * inv;
            if (sub == 0) { g_edone[e] = 0; g_ecnt[e] = 0; }   // ready for next replay
        }
    }
}

extern "C" void kernel_launch(void* const* d_in, const int* in_sizes, int n_in,
                              void* d_out, int out_size) {
    const float* ef   = (const float*)d_in[0];
    const int*   eids = (const int*)  d_in[1];
    const int*   tri  = (const int*)  d_in[2];
    const float* Wq = (const float*)d_in[3];  const float* bq = (const float*)d_in[4];
    const float* Wk = (const float*)d_in[5];  const float* bk = (const float*)d_in[6];
    const float* Wv = (const float*)d_in[7];  const float* bv = (const float*)d_in[8];
    const float* W1 = (const float*)d_in[9];  const float* b1 = (const float*)d_in[10];
    const float* g1 = (const float*)d_in[11]; const float* B1 = (const float*)d_in[12];
    const float* rw = (const float*)d_in[13];
    const float* Wr = (const float*)d_in[14]; const float* br = (const float*)d_in[15];
    const float* g2 = (const float*)d_in[16]; const float* B2 = (const float*)d_in[17];
    const float* W2 = (const float*)d_in[18]; const float* b2 = (const float*)d_in[19];
    const float* W3 = (const float*)d_in[20]; const float* b3 = (const float*)d_in[21];
    float* out = (float*)d_out;

    k_fused<<<NB, TPB>>>(ef, eids, tri, Wq, bq, Wk, bk, Wv, bv,
                         W1, b1, g1, B1, rw, Wr, br, g2, B2, W2, b2, W3, b3, out);
}

// round 14
// speedup vs baseline: 1.1026x; 1.1026x over previous
#include <cuda_runtime.h>
#include <math.h>

#define N       12288
#define D_K     8
#define H1      32
#define H2      16
#define N_EDGES 6144
#define N_TRI   4096
#define CAP     64
#define ECAP    32
#define NB      128
#define TPB     384
#define RPB     96    // rows per block (TPB/4)

// ---------------- device scratch (zero-initialized at module load) ----------------
__device__ float    g_kv[N_TRI * CAP * 16];  // per-slot: k[0:8), v[8:16)
__device__ float    g_logits[N];
__device__ int      g_cnt[N_TRI];           // returns to 0 every call (tri completion)
__device__ int      g_tdone[N_TRI];         // returns to 0 every call
__device__ int      g_ecnt[N_EDGES];        // returns to 0 every call (edge completion)
__device__ int      g_edone[N_EDGES];       // returns to 0 every call
__device__ int      g_emem[N_EDGES * ECAP];
__device__ unsigned g_bar1;                 // monotonic ticket counter (never reset)

__device__ __forceinline__ float gelu_exact(float x) {
    return 0.5f * x * (1.0f + erff(x * 0.70710678118654752f));
}

// acq_rel gpu-scope atomic add: release orders prior stores (logit) before the
// RMW; acquire orders subsequent loads after it. No CCTL.IVALL L1 flush.
__device__ __forceinline__ int atom_add_acqrel(int* p, int v) {
    int old;
    asm volatile("atom.acq_rel.gpu.global.add.s32 %0, [%1], %2;"
                 : "=r"(old) : "l"(p), "r"(v) : "memory");
    return old;
}

// ticket grid barrier — monotonic across graph replays, no reset required.
// safe: 128 blocks, 1 block/SM, strictly one co-resident wave on 148 SMs.
__device__ __forceinline__ void grid_barrier_ticket(unsigned* ctr) {
    __syncthreads();
    if (threadIdx.x == 0) {
        __threadfence();
        unsigned t0 = atomicAdd(ctr, 1u);
        unsigned target = t0 - (t0 % NB) + NB;
        while (*(volatile unsigned*)ctr < target) {}
        __threadfence();
    }
    __syncthreads();
}

__global__ __launch_bounds__(TPB, 1)
void k_fused(const float* __restrict__ ef, const int* __restrict__ eids,
             const int* __restrict__ tri,
             const float* __restrict__ Wq, const float* __restrict__ bq,
             const float* __restrict__ Wk, const float* __restrict__ bk,
             const float* __restrict__ Wv, const float* __restrict__ bv,
             const float* __restrict__ W1, const float* __restrict__ b1,
             const float* __restrict__ ln1g, const float* __restrict__ ln1b,
             const float* __restrict__ rmsw,
             const float* __restrict__ Wr, const float* __restrict__ br,
             const float* __restrict__ ln2g, const float* __restrict__ ln2b,
             const float* __restrict__ W2, const float* __restrict__ b2,
             const float* __restrict__ W3, const float* __restrict__ b3,
             float* __restrict__ out) {
    // padded shared weights (odd strides -> conflict-free for 4-lane groups)
    __shared__ float sW1[H1 * 9];        // [o*9 + k], k<8
    __shared__ float sWr[H1 * 33];       // [o*33 + k], k<32
    __shared__ float sW2[H2 * 33];       // [o*33 + k], k<32
    __shared__ float sb1[H1], sg1[H1], sB1[H1], srw[H1], sbr[H1], sg2[H1], sB2[H1];
    __shared__ float sb2[H2], sW3[H2];
    __shared__ float sb3;
    __shared__ float sh[RPB * 33];       // per-row 32-vector scratch, padded

    const int tid = threadIdx.x;
    const int sub = tid & 3;             // lane within 4-lane row group
    const int rl  = tid >> 2;            // local row
    const int i   = blockIdx.x * RPB + rl;
    const int lane = tid & 31;
    const unsigned gmask = 0xFu << (lane & ~3);   // this group's shuffle mask

    // ---- stage weights (overlaps phase 1; consumed only after the barrier) ----
    for (int j = tid; j < H1 * D_K; j += TPB) sW1[(j >> 3) * 9  + (j & 7)]  = W1[j];
    for (int j = tid; j < H1 * H1;  j += TPB) sWr[(j >> 5) * 33 + (j & 31)] = Wr[j];
    for (int j = tid; j < H2 * H1;  j += TPB) sW2[(j >> 5) * 33 + (j & 31)] = W2[j];
    if (tid < H1) {
        sb1[tid] = b1[tid];   sg1[tid] = ln1g[tid]; sB1[tid] = ln1b[tid];
        srw[tid] = rmsw[tid]; sbr[tid] = br[tid];
        sg2[tid] = ln2g[tid]; sB2[tid] = ln2b[tid];
    }
    if (tid < H2) { sb2[tid] = b2[tid]; sW3[tid] = W3[tid]; }
    if (tid == 0) sb3 = b3[0];

    // ============ Phase 1: qkv (2 dims/lane) + slot-indexed k/v store ========
    float2 qv;                            // kept live for phase 2
    const int t = tri[i];
    const int e = eids[i];
    {
        float x0 = ef[2 * i + 0];
        float x1 = ef[2 * i + 1];
        int o0 = 2 * sub;
        float2 kv, vv;
        qv.x = fmaf(x0, Wq[o0*2],     fmaf(x1, Wq[o0*2+1],     bq[o0]));
        qv.y = fmaf(x0, Wq[(o0+1)*2], fmaf(x1, Wq[(o0+1)*2+1], bq[o0+1]));
        kv.x = fmaf(x0, Wk[o0*2],     fmaf(x1, Wk[o0*2+1],     bk[o0]));
        kv.y = fmaf(x0, Wk[(o0+1)*2], fmaf(x1, Wk[(o0+1)*2+1], bk[o0+1]));
        vv.x = fmaf(x0, Wv[o0*2],     fmaf(x1, Wv[o0*2+1],     bv[o0]));
        vv.y = fmaf(x0, Wv[(o0+1)*2], fmaf(x1, Wv[(o0+1)*2+1], bv[o0+1]));
        int p = 0;
        if (sub == 0) {
            p = atomicAdd(&g_cnt[t], 1);
            int pe = atomicAdd(&g_ecnt[e], 1);
            if (pe < ECAP) g_emem[e * ECAP + pe] = i;
        }
        p = __shfl_sync(gmask, p, 0, 4);
        if (p < CAP) {
            float2* dst = (float2*)&g_kv[((size_t)t * CAP + p) * 16];
            dst[sub]     = kv;            // k dims [2sub, 2sub+1]
            dst[4 + sub] = vv;            // v dims [2sub, 2sub+1]
        }
    }

    grid_barrier_ticket(&g_bar1);

    // ====== Phase 2: attention + MLP -> logits + dataflow completions ======
    {
        // full q[8] to every lane via intra-group broadcast
        float q[D_K];
#pragma unroll
        for (int s2 = 0; s2 < 4; s2++) {
            q[2*s2]   = __shfl_sync(gmask, qv.x, s2, 4);
            q[2*s2+1] = __shfl_sync(gmask, qv.y, s2, 4);
        }

        const float isq = 0.35355339059327373f;  // 1/sqrt(8)
        const float4* kvb = (const float4*)&g_kv[(size_t)t * CAP * 16];

        // speculative: issue count loads AND first-slot kv loads concurrently —
        // slots beyond c hold stale data; contribution predicated to 0 below.
        const int cc  = g_cnt[t];            // final after barrier
        const int tot = g_ecnt[e];           // final after barrier
        float4 ka = kvb[sub * 4 + 0];
        float4 kb = kvb[sub * 4 + 1];
        float4 va = kvb[sub * 4 + 2];
        float4 vb = kvb[sub * 4 + 3];
        const int c = min(cc, CAP);

        float se = 0.0f, acc[D_K];
#pragma unroll
        for (int o = 0; o < D_K; o++) acc[o] = 0.0f;
        {
            float p = q[0]*ka.x + q[1]*ka.y + q[2]*ka.z + q[3]*ka.w
                    + q[4]*kb.x + q[5]*kb.y + q[6]*kb.z + q[7]*kb.w;
            float ex = (sub < c) ? __expf(p * isq) : 0.0f;
            se += ex;
            acc[0] = fmaf(ex, va.x, acc[0]); acc[1] = fmaf(ex, va.y, acc[1]);
            acc[2] = fmaf(ex, va.z, acc[2]); acc[3] = fmaf(ex, va.w, acc[3]);
            acc[4] = fmaf(ex, vb.x, acc[4]); acc[5] = fmaf(ex, vb.y, acc[5]);
            acc[6] = fmaf(ex, vb.z, acc[6]); acc[7] = fmaf(ex, vb.w, acc[7]);
        }
        for (int jj = sub + 4; jj < c; jj += 4) {   // rare tail (c > 4)
            float4 ka2 = kvb[jj * 4 + 0];
            float4 kb2 = kvb[jj * 4 + 1];
            float4 va2 = kvb[jj * 4 + 2];
            float4 vb2 = kvb[jj * 4 + 3];
            float p = q[0]*ka2.x + q[1]*ka2.y + q[2]*ka2.z + q[3]*ka2.w
                    + q[4]*kb2.x + q[5]*kb2.y + q[6]*kb2.z + q[7]*kb2.w;
            float ex = __expf(p * isq);
            se += ex;
            acc[0] = fmaf(ex, va2.x, acc[0]); acc[1] = fmaf(ex, va2.y, acc[1]);
            acc[2] = fmaf(ex, va2.z, acc[2]); acc[3] = fmaf(ex, va2.w, acc[3]);
            acc[4] = fmaf(ex, vb2.x, acc[4]); acc[5] = fmaf(ex, vb2.y, acc[5]);
            acc[6] = fmaf(ex, vb2.z, acc[6]); acc[7] = fmaf(ex, vb2.w, acc[7]);
        }
        // triangle completion ticket (reads of g_kv for t are done; relaxed ok)
        int dt = 0;
        if (sub == 0) dt = atomicAdd(&g_tdone[t], 1);

        se += __shfl_xor_sync(gmask, se, 1);
        se += __shfl_xor_sync(gmask, se, 2);
#pragma unroll
        for (int o = 0; o < D_K; o++) {
            acc[o] += __shfl_xor_sync(gmask, acc[o], 1);
            acc[o] += __shfl_xor_sync(gmask, acc[o], 2);
        }
        float inv_se = 1.0f / se;
        float att[D_K];
#pragma unroll
        for (int o = 0; o < D_K; o++) att[o] = acc[o] * inv_se;

        // ---- MLP: this lane owns outputs o = 8*sub .. 8*sub+7 ----
        const int ob = 8 * sub;
        float h[8];
#pragma unroll
        for (int oi = 0; oi < 8; oi++) {
            int o = ob + oi;
            float s = sb1[o];
#pragma unroll
            for (int kk = 0; kk < D_K; kk++) s = fmaf(att[kk], sW1[o * 9 + kk], s);
            h[oi] = s;
        }
        // layernorm 1 + gelu (one-round: concurrent sum & sumsq trees)
        {
            float ls = 0.0f, lq = 0.0f;
#pragma unroll
            for (int oi = 0; oi < 8; oi++) { ls += h[oi]; lq = fmaf(h[oi], h[oi], lq); }
            ls += __shfl_xor_sync(gmask, ls, 1);
            lq += __shfl_xor_sync(gmask, lq, 1);
            ls += __shfl_xor_sync(gmask, ls, 2);
            lq += __shfl_xor_sync(gmask, lq, 2);
            float mu  = ls * (1.0f / H1);
            float var = fmaf(-mu, mu, lq * (1.0f / H1));   // E[x^2] - mu^2
            float inv = rsqrtf(var + 1e-5f);
#pragma unroll
            for (int oi = 0; oi < 8; oi++)
                h[oi] = gelu_exact((h[oi] - mu) * inv * sg1[ob + oi] + sB1[ob + oi]);
        }
        // rmsnorm -> shared -> linear -> relu -> residual
        {
            float ss = 0.0f;
#pragma unroll
            for (int oi = 0; oi < 8; oi++) ss = fmaf(h[oi], h[oi], ss);
            ss += __shfl_xor_sync(gmask, ss, 1);
            ss += __shfl_xor_sync(gmask, ss, 2);
            float rms = sqrtf(ss * (1.0f / H1));
            float rinv = 1.0f / (rms + 1e-6f);
#pragma unroll
            for (int oi = 0; oi < 8; oi++)
                sh[rl * 33 + ob + oi] = h[oi] * rinv * srw[ob + oi];
            __syncwarp();
#pragma unroll
            for (int oi = 0; oi < 8; oi++) {
                int o = ob + oi;
                float s = sbr[o];
#pragma unroll
                for (int kk = 0; kk < H1; kk++)
                    s = fmaf(sh[rl * 33 + kk], sWr[o * 33 + kk], s);
                h[oi] += fmaxf(s, 0.0f);
            }
        }
        // layernorm 2 (one-round)
        {
            float ls = 0.0f, lq = 0.0f;
#pragma unroll
            for (int oi = 0; oi < 8; oi++) { ls += h[oi]; lq = fmaf(h[oi], h[oi], lq); }
            ls += __shfl_xor_sync(gmask, ls, 1);
            lq += __shfl_xor_sync(gmask, lq, 1);
            ls += __shfl_xor_sync(gmask, ls, 2);
            lq += __shfl_xor_sync(gmask, lq, 2);
            float mu  = ls * (1.0f / H1);
            float var = fmaf(-mu, mu, lq * (1.0f / H1));
            float inv = rsqrtf(var + 1e-5f);
#pragma unroll
            for (int oi = 0; oi < 8; oi++)
                h[oi] = (h[oi] - mu) * inv * sg2[ob + oi] + sB2[ob + oi];
        }
        // publish h, then linear 32->16 + gelu + linear 16->1 (4 outputs/lane)
        __syncwarp();
#pragma unroll
        for (int oi = 0; oi < 8; oi++) sh[rl * 33 + ob + oi] = h[oi];
        __syncwarp();
        float part = 0.0f;
#pragma unroll
        for (int oi = 0; oi < 4; oi++) {
            int o = 4 * sub + oi;
            float s = sb2[o];
#pragma unroll
            for (int kk = 0; kk < H1; kk++)
                s = fmaf(sh[rl * 33 + kk], sW2[o * 33 + kk], s);
            part = fmaf(gelu_exact(s), sW3[o], part);
        }
        part += __shfl_xor_sync(gmask, part, 1);
        part += __shfl_xor_sync(gmask, part, 2);
        // all 4 lanes now hold the full logit
        float lg = part + sb3;

        // ---- publish logit + edge completion (acq_rel atomic, no L1 flush) ----
        int elast = 0;
        if (sub == 0) {
            g_logits[i] = lg;                      // write-through to L2
            int d = atom_add_acqrel(&g_edone[e], 1);  // release: logit ordered first
            elast = (d == tot - 1);
            // triangle completion: all members have read g_cnt/g_kv by now
            if (dt == cc - 1) { g_cnt[t] = 0; g_tdone[t] = 0; }
        }
        elast = __shfl_sync(gmask, elast, 0, 4);

        if (elast) {
            // acquire half of the RMW ordered our subsequent loads; each
            // g_logits[j] is read exactly once per SM per launch -> no stale L1
            int m = min(tot, ECAP);
            float lv[8];
            int   jx[8];
            int   n = 0;
            float mx = -1e30f;
            for (int jj = sub; jj < m; jj += 4) {
                int j = g_emem[e * ECAP + jj];
                float l = g_logits[j];
                jx[n] = j; lv[n] = l; n++;
                mx = fmaxf(mx, l);
            }
            mx = fmaxf(mx, __shfl_xor_sync(gmask, mx, 1));
            mx = fmaxf(mx, __shfl_xor_sync(gmask, mx, 2));
            float s = 0.0f;
            for (int u = 0; u < n; u++) { lv[u] = __expf(lv[u] - mx); s += lv[u]; }
            s += __shfl_xor_sync(gmask, s, 1);
            s += __shfl_xor_sync(gmask, s, 2);
            float inv = 1.0f / s;
            for (int u = 0; u < n; u++) out[jx[u]] = lv[u] * inv;
            if (sub == 0) { g_edone[e] = 0; g_ecnt[e] = 0; }   // ready for next replay
        }
    }
}

extern "C" void kernel_launch(void* const* d_in, const int* in_sizes, int n_in,
                              void* d_out, int out_size) {
    const float* ef   = (const float*)d_in[0];
    const int*   eids = (const int*)  d_in[1];
    const int*   tri  = (const int*)  d_in[2];
    const float* Wq = (const float*)d_in[3];  const float* bq = (const float*)d_in[4];
    const float* Wk = (const float*)d_in[5];  const float* bk = (const float*)d_in[6];
    const float* Wv = (const float*)d_in[7];  const float* bv = (const float*)d_in[8];
    const float* W1 = (const float*)d_in[9];  const float* b1 = (const float*)d_in[10];
    const float* g1 = (const float*)d_in[11]; const float* B1 = (const float*)d_in[12];
    const float* rw = (const float*)d_in[13];
    const float* Wr = (const float*)d_in[14]; const float* br = (const float*)d_in[15];
    const float* g2 = (const float*)d_in[16]; const float* B2 = (const float*)d_in[17];
    const float* W2 = (const float*)d_in[18]; const float* b2 = (const float*)d_in[19];
    const float* W3 = (const float*)d_in[20]; const float* b3 = (const float*)d_in[21];
    float* out = (float*)d_out;

    k_fused<<<NB, TPB>>>(ef, eids, tri, Wq, bq, Wk, bk, Wv, bv,
                         W1, b1, g1, B1, rw, Wr, br, g2, B2, W2, b2, W3, b3, out);
}

// round 15
// speedup vs baseline: 1.1193x; 1.0152x over previous
#include <cuda_runtime.h>
#include <math.h>

#define N       12288
#define D_K     8
#define H1      32
#define H2      16
#define N_EDGES 6144
#define N_TRI   4096
#define CAP     64
#define ECAP    32
#define NB      128
#define TPB     384
#define RPB     96    // rows per block (TPB/4)

// ---------------- device scratch (zero-initialized at module load) ----------------
__device__ float    g_kv[N_TRI * CAP * 16];     // per-slot: k[0:8), v[8:16)
__device__ float2   g_epk[N_EDGES * ECAP];      // per-edge-slot: (exp(logit), idx)
__device__ int      g_cnt[N_TRI];           // returns to 0 every call (tri completion)
__device__ int      g_tdone[N_TRI];         // returns to 0 every call
__device__ int      g_ecnt[N_EDGES];        // returns to 0 every call (edge completion)
__device__ int      g_edone[N_EDGES];       // returns to 0 every call
__device__ unsigned g_bar1;                 // monotonic ticket counter (never reset)

__device__ __forceinline__ float gelu_exact(float x) {
    return 0.5f * x * (1.0f + erff(x * 0.70710678118654752f));
}

// acq_rel gpu-scope atomic add: release orders prior stores before the RMW;
// acquire orders subsequent loads after it. No CCTL.IVALL L1 flush.
__device__ __forceinline__ int atom_add_acqrel(int* p, int v) {
    int old;
    asm volatile("atom.acq_rel.gpu.global.add.s32 %0, [%1], %2;"
                 : "=r"(old) : "l"(p), "r"(v) : "memory");
    return old;
}

// ticket grid barrier — monotonic across graph replays, no reset required.
// safe: 128 blocks, 1 block/SM, strictly one co-resident wave on 148 SMs.
__device__ __forceinline__ void grid_barrier_ticket(unsigned* ctr) {
    __syncthreads();
    if (threadIdx.x == 0) {
        __threadfence();
        unsigned t0 = atomicAdd(ctr, 1u);
        unsigned target = t0 - (t0 % NB) + NB;
        while (*(volatile unsigned*)ctr < target) {}
        __threadfence();
    }
    __syncthreads();
}

__global__ __launch_bounds__(TPB, 1)
void k_fused(const float* __restrict__ ef, const int* __restrict__ eids,
             const int* __restrict__ tri,
             const float* __restrict__ Wq, const float* __restrict__ bq,
             const float* __restrict__ Wk, const float* __restrict__ bk,
             const float* __restrict__ Wv, const float* __restrict__ bv,
             const float* __restrict__ W1, const float* __restrict__ b1,
             const float* __restrict__ ln1g, const float* __restrict__ ln1b,
             const float* __restrict__ rmsw,
             const float* __restrict__ Wr, const float* __restrict__ br,
             const float* __restrict__ ln2g, const float* __restrict__ ln2b,
             const float* __restrict__ W2, const float* __restrict__ b2,
             const float* __restrict__ W3, const float* __restrict__ b3,
             float* __restrict__ out) {
    // sW1: [o*9+k] scalar (odd stride, conflict-free).
    // sWrT/sW2T: TRANSPOSED [kk*stride + o] so the float4 weight loads are
    // indexed by o (lane spacing 8*sub / 4*sub -> banks 8 / 4 apart, conflict-
    // free), while the activation load sh[rl*33+kk] is a 4-lane broadcast.
    __shared__ float sW1[H1 * 9];
    __shared__ __align__(16) float sWrT[H1 * 36];   // [kk*36 + o], o<32
    __shared__ __align__(16) float sW2T[H1 * 20];   // [kk*20 + o], o<16
    __shared__ float sb1[H1], sg1[H1], sB1[H1], srw[H1], sbr[H1], sg2[H1], sB2[H1];
    __shared__ float sb2[H2], sW3[H2];
    __shared__ float sb3;
    __shared__ float sh[RPB * 33];       // per-row 32-vector scratch, padded

    const int tid = threadIdx.x;
    const int sub = tid & 3;             // lane within 4-lane row group
    const int rl  = tid >> 2;            // local row
    const int i   = blockIdx.x * RPB + rl;
    const int lane = tid & 31;
    const unsigned gmask = 0xFu << (lane & ~3);   // this group's shuffle mask

    // ---- stage weights (overlaps phase 1; consumed only after the barrier) ----
    for (int j = tid; j < H1 * D_K; j += TPB) sW1[(j >> 3) * 9 + (j & 7)] = W1[j];
    for (int j = tid; j < H1 * H1;  j += TPB) sWrT[(j & 31) * 36 + (j >> 5)] = Wr[j];
    for (int j = tid; j < H2 * H1;  j += TPB) sW2T[(j & 31) * 20 + (j >> 5)] = W2[j];
    if (tid < H1) {
        sb1[tid] = b1[tid];   sg1[tid] = ln1g[tid]; sB1[tid] = ln1b[tid];
        srw[tid] = rmsw[tid]; sbr[tid] = br[tid];
        sg2[tid] = ln2g[tid]; sB2[tid] = ln2b[tid];
    }
    if (tid < H2) { sb2[tid] = b2[tid]; sW3[tid] = W3[tid]; }
    if (tid == 0) sb3 = b3[0];

    // ============ Phase 1: qkv (2 dims/lane) + slot-indexed k/v store ========
    float2 qv;                            // kept live for phase 2
    const int t = tri[i];
    const int e = eids[i];
    int pe = 0;                           // this row's edge slot (sub==0 only)
    {
        float x0 = ef[2 * i + 0];
        float x1 = ef[2 * i + 1];
        int o0 = 2 * sub;
        float2 kv, vv;
        qv.x = fmaf(x0, Wq[o0*2],     fmaf(x1, Wq[o0*2+1],     bq[o0]));
        qv.y = fmaf(x0, Wq[(o0+1)*2], fmaf(x1, Wq[(o0+1)*2+1], bq[o0+1]));
        kv.x = fmaf(x0, Wk[o0*2],     fmaf(x1, Wk[o0*2+1],     bk[o0]));
        kv.y = fmaf(x0, Wk[(o0+1)*2], fmaf(x1, Wk[(o0+1)*2+1], bk[o0+1]));
        vv.x = fmaf(x0, Wv[o0*2],     fmaf(x1, Wv[o0*2+1],     bv[o0]));
        vv.y = fmaf(x0, Wv[(o0+1)*2], fmaf(x1, Wv[(o0+1)*2+1], bv[o0+1]));
        int p = 0;
        if (sub == 0) {
            p = atomicAdd(&g_cnt[t], 1);
            pe = atomicAdd(&g_ecnt[e], 1);
        }
        p = __shfl_sync(gmask, p, 0, 4);
        if (p < CAP) {
            float2* dst = (float2*)&g_kv[((size_t)t * CAP + p) * 16];
            dst[sub]     = kv;            // k dims [2sub, 2sub+1]
            dst[4 + sub] = vv;            // v dims [2sub, 2sub+1]
        }
    }

    grid_barrier_ticket(&g_bar1);

    // ====== Phase 2: attention + MLP -> exp(logit) + dataflow completions ======
    {
        // full q[8] to every lane via intra-group broadcast
        float q[D_K];
#pragma unroll
        for (int s2 = 0; s2 < 4; s2++) {
            q[2*s2]   = __shfl_sync(gmask, qv.x, s2, 4);
            q[2*s2+1] = __shfl_sync(gmask, qv.y, s2, 4);
        }

        const float isq = 0.35355339059327373f;  // 1/sqrt(8)
        const float4* kvb = (const float4*)&g_kv[(size_t)t * CAP * 16];

        const int cc  = g_cnt[t];            // final after barrier
        const int tot = g_ecnt[e];           // final after barrier
        const int c   = min(cc, CAP);

        float se = 0.0f, acc[D_K];
#pragma unroll
        for (int o = 0; o < D_K; o++) acc[o] = 0.0f;
        for (int jj = sub; jj < c; jj += 4) {
            float4 ka = kvb[jj * 4 + 0];
            float4 kb = kvb[jj * 4 + 1];
            float4 va = kvb[jj * 4 + 2];
            float4 vb = kvb[jj * 4 + 3];
            float p = q[0]*ka.x + q[1]*ka.y + q[2]*ka.z + q[3]*ka.w
                    + q[4]*kb.x + q[5]*kb.y + q[6]*kb.z + q[7]*kb.w;
            float ex = __expf(p * isq);      // scores bounded; normalization identical
            se += ex;
            acc[0] = fmaf(ex, va.x, acc[0]); acc[1] = fmaf(ex, va.y, acc[1]);
            acc[2] = fmaf(ex, va.z, acc[2]); acc[3] = fmaf(ex, va.w, acc[3]);
            acc[4] = fmaf(ex, vb.x, acc[4]); acc[5] = fmaf(ex, vb.y, acc[5]);
            acc[6] = fmaf(ex, vb.z, acc[6]); acc[7] = fmaf(ex, vb.w, acc[7]);
        }
        // triangle completion ticket (reads of g_kv for t are done; relaxed ok)
        int dt = 0;
        if (sub == 0) dt = atomicAdd(&g_tdone[t], 1);

        se += __shfl_xor_sync(gmask, se, 1);
        se += __shfl_xor_sync(gmask, se, 2);
#pragma unroll
        for (int o = 0; o < D_K; o++) {
            acc[o] += __shfl_xor_sync(gmask, acc[o], 1);
            acc[o] += __shfl_xor_sync(gmask, acc[o], 2);
        }
        float inv_se = 1.0f / se;
        float att[D_K];
#pragma unroll
        for (int o = 0; o < D_K; o++) att[o] = acc[o] * inv_se;

        // ---- MLP: this lane owns outputs o = 8*sub .. 8*sub+7 ----
        const int ob = 8 * sub;
        float h[8];
#pragma unroll
        for (int oi = 0; oi < 8; oi++) {
            int o = ob + oi;
            float s = sb1[o];
#pragma unroll
            for (int kk = 0; kk < D_K; kk++) s = fmaf(att[kk], sW1[o * 9 + kk], s);
            h[oi] = s;
        }
        // layernorm 1 + gelu (one-round: concurrent sum & sumsq trees)
        {
            float ls = 0.0f, lq = 0.0f;
#pragma unroll
            for (int oi = 0; oi < 8; oi++) { ls += h[oi]; lq = fmaf(h[oi], h[oi], lq); }
            ls += __shfl_xor_sync(gmask, ls, 1);
            lq += __shfl_xor_sync(gmask, lq, 1);
            ls += __shfl_xor_sync(gmask, ls, 2);
            lq += __shfl_xor_sync(gmask, lq, 2);
            float mu  = ls * (1.0f / H1);
            float var = fmaf(-mu, mu, lq * (1.0f / H1));   // E[x^2] - mu^2
            float inv = rsqrtf(var + 1e-5f);
#pragma unroll
            for (int oi = 0; oi < 8; oi++)
                h[oi] = gelu_exact((h[oi] - mu) * inv * sg1[ob + oi] + sB1[ob + oi]);
        }
        // rmsnorm -> shared -> transposed GEMV -> relu -> residual
        {
            float ss = 0.0f;
#pragma unroll
            for (int oi = 0; oi < 8; oi++) ss = fmaf(h[oi], h[oi], ss);
            ss += __shfl_xor_sync(gmask, ss, 1);
            ss += __shfl_xor_sync(gmask, ss, 2);
            float rms = sqrtf(ss * (1.0f / H1));
            float rinv = 1.0f / (rms + 1e-6f);
#pragma unroll
            for (int oi = 0; oi < 8; oi++)
                sh[rl * 33 + ob + oi] = h[oi] * rinv * srw[ob + oi];
            __syncwarp();
            float s8[8];
#pragma unroll
            for (int oi = 0; oi < 8; oi++) s8[oi] = sbr[ob + oi];
#pragma unroll
            for (int kk = 0; kk < H1; kk++) {
                float x = sh[rl * 33 + kk];                    // 4-lane broadcast
                const float4* wp = (const float4*)&sWrT[kk * 36 + ob];
                float4 w0 = wp[0], w1 = wp[1];                 // conflict-free
                s8[0] = fmaf(x, w0.x, s8[0]); s8[1] = fmaf(x, w0.y, s8[1]);
                s8[2] = fmaf(x, w0.z, s8[2]); s8[3] = fmaf(x, w0.w, s8[3]);
                s8[4] = fmaf(x, w1.x, s8[4]); s8[5] = fmaf(x, w1.y, s8[5]);
                s8[6] = fmaf(x, w1.z, s8[6]); s8[7] = fmaf(x, w1.w, s8[7]);
            }
#pragma unroll
            for (int oi = 0; oi < 8; oi++) h[oi] += fmaxf(s8[oi], 0.0f);
        }
        // layernorm 2 (one-round)
        {
            float ls = 0.0f, lq = 0.0f;
#pragma unroll
            for (int oi = 0; oi < 8; oi++) { ls += h[oi]; lq = fmaf(h[oi], h[oi], lq); }
            ls += __shfl_xor_sync(gmask, ls, 1);
            lq += __shfl_xor_sync(gmask, lq, 1);
            ls += __shfl_xor_sync(gmask, ls, 2);
            lq += __shfl_xor_sync(gmask, lq, 2);
            float mu  = ls * (1.0f / H1);
            float var = fmaf(-mu, mu, lq * (1.0f / H1));
            float inv = rsqrtf(var + 1e-5f);
#pragma unroll
            for (int oi = 0; oi < 8; oi++)
                h[oi] = (h[oi] - mu) * inv * sg2[ob + oi] + sB2[ob + oi];
        }
        // publish h, transposed 32->16 GEMV + gelu + 16->1
        __syncwarp();
#pragma unroll
        for (int oi = 0; oi < 8; oi++) sh[rl * 33 + ob + oi] = h[oi];
        __syncwarp();
        float part = 0.0f;
        {
            float s4[4];
#pragma unroll
            for (int oi = 0; oi < 4; oi++) s4[oi] = sb2[4 * sub + oi];
#pragma unroll
            for (int kk = 0; kk < H1; kk++) {
                float x = sh[rl * 33 + kk];
                float4 w = *(const float4*)&sW2T[kk * 20 + 4 * sub];
                s4[0] = fmaf(x, w.x, s4[0]); s4[1] = fmaf(x, w.y, s4[1]);
                s4[2] = fmaf(x, w.z, s4[2]); s4[3] = fmaf(x, w.w, s4[3]);
            }
#pragma unroll
            for (int oi = 0; oi < 4; oi++)
                part = fmaf(gelu_exact(s4[oi]), sW3[4 * sub + oi], part);
        }
        part += __shfl_xor_sync(gmask, part, 1);
        part += __shfl_xor_sync(gmask, part, 2);
        float lg = part + sb3;               // all lanes hold the logit

        // ---- publish exp(logit) into slot + edge completion ----
        // max-subtraction dropped: weights e_j / sum(e) identical, logits bounded.
        int elast = 0;
        if (sub == 0) {
            g_epk[e * ECAP + min(pe, ECAP - 1)] =
                make_float2(__expf(lg), __int_as_float(i));
            int d = atom_add_acqrel(&g_edone[e], 1);  // release: slot ordered first
            elast = (d == tot - 1);
            // triangle completion: all members have read g_cnt/g_kv by now
            if (dt == cc - 1) { g_cnt[t] = 0; g_tdone[t] = 0; }
        }
        elast = __shfl_sync(gmask, elast, 0, 4);

        if (elast) {
            // single parallel L2 round: slot-indexed (e, idx) pairs, no indirection
            int m = min(tot, ECAP);
            float2 pk[8];
            int n = 0;
            float s = 0.0f;
            for (int jj = sub; jj < m; jj += 4) {
                pk[n] = g_epk[e * ECAP + jj];
                s += pk[n].x;
                n++;
            }
            s += __shfl_xor_sync(gmask, s, 1);
            s += __shfl_xor_sync(gmask, s, 2);
            float inv = 1.0f / s;
            for (int u = 0; u < n; u++)
                out[__float_as_int(pk[u].y)] = pk[u].x * inv;
            if (sub == 0) { g_edone[e] = 0; g_ecnt[e] = 0; }   // ready for next replay
        }
    }
}

extern "C" void kernel_launch(void* const* d_in, const int* in_sizes, int n_in,
                              void* d_out, int out_size) {
    const float* ef   = (const float*)d_in[0];
    const int*   eids = (const int*)  d_in[1];
    const int*   tri  = (const int*)  d_in[2];
    const float* Wq = (const float*)d_in[3];  const float* bq = (const float*)d_in[4];
    const float* Wk = (const float*)d_in[5];  const float* bk = (const float*)d_in[6];
    const float* Wv = (const float*)d_in[7];  const float* bv = (const float*)d_in[8];
    const float* W1 = (const float*)d_in[9];  const float* b1 = (const float*)d_in[10];
    const float* g1 = (const float*)d_in[11]; const float* B1 = (const float*)d_in[12];
    const float* rw = (const float*)d_in[13];
    const float* Wr = (const float*)d_in[14]; const float* br = (const float*)d_in[15];
    const float* g2 = (const float*)d_in[16]; const float* B2 = (const float*)d_in[17];
    const float* W2 = (const float*)d_in[18]; const float* b2 = (const float*)d_in[19];
    const float* W3 = (const float*)d_in[20]; const float* b3 = (const float*)d_in[21];
    float* out = (float*)d_out;

    k_fused<<<NB, TPB>>>(ef, eids, tri, Wq, bq, Wk, bk, Wv, bv,
                         W1, b1, g1, B1, rw, Wr, br, g2, B2, W2, b2, W3, b3, out);
}